// round 1
// baseline (speedup 1.0000x reference)
#include <cuda_runtime.h>
#include <cstdint>

#define N_MAX 100000
#define IN_F  512
#define HID   16
#define NCLS  7

// ---- scratch (no allocations allowed) ----
__device__ float  s_dinv[N_MAX];
__device__ float4 s_g1  [N_MAX * 4];   // [N][16] floats: dinv*x@W1
__device__ float4 s_agg1[N_MAX * 4];   // layer-1 accumulator
__device__ float4 s_g2  [N_MAX * 2];   // [N][8] floats (col 7 = 0 pad)
__device__ float4 s_agg2[N_MAX * 2];   // layer-2 accumulator

// ---- f32x2 packed math (sm_100+) ----
#define FMA2(d, a, b, c) asm("fma.rn.f32x2 %0, %1, %2, %3;" : "=l"(d) : "l"(a), "l"(b), "l"(c))
#define ADD2(d, a, b)    asm("add.rn.f32x2 %0, %1, %2;"     : "=l"(d) : "l"(a), "l"(b))
#define MUL2(d, a, b)    asm("mul.rn.f32x2 %0, %1, %2;"     : "=l"(d) : "l"(a), "l"(b))
#define PACK2(d, s)      asm("mov.b64 %0, {%1, %1};"        : "=l"(d) : "r"(__float_as_uint(s)))

// vector reduction to global (sm_90+): one 16B L2 atomic instead of 4 scalar ones
#define RED4(p, a, b, c, d) \
    asm volatile("red.global.add.v4.f32 [%0], {%1, %2, %3, %4};" \
                 :: "l"(p), "f"(a), "f"(b), "f"(c), "f"(d) : "memory")

// ---------------- degree / dinv ----------------
__global__ void k_init(int n) {
    int i = blockIdx.x * blockDim.x + threadIdx.x;
    if (i < n) s_dinv[i] = 1.0f;                 // self-loop counts once
}

__global__ void k_deg(const int* __restrict__ dst, int e) {
    int i = blockIdx.x * blockDim.x + threadIdx.x;
    if (i < e) atomicAdd(&s_dinv[dst[i]], 1.0f);
}

__global__ void k_rsqrt(int n) {
    int i = blockIdx.x * blockDim.x + threadIdx.x;
    if (i < n) s_dinv[i] = rsqrtf(s_dinv[i]);    // deg >= 1 always
}

// ---------------- layer-1 GEMM: g1[i] = dinv[i] * (x[i] @ W1) ----------------
// One warp per row. Lane l owns k = l + 32*i (i=0..15). W1 in smem with pitch 18
// floats (72B): per-lane LDS.64 stride = 18 words -> bank step 18, which covers
// all 32 banks over a 16-lane phase => conflict-free. Accumulate in f32x2 pairs.
__global__ void __launch_bounds__(256) k_gemm1(const float* __restrict__ x,
                                               const float* __restrict__ W1, int n) {
    __shared__ float Wp[IN_F * 18];
    for (int i = threadIdx.x; i < IN_F * HID; i += 256)
        Wp[(i >> 4) * 18 + (i & 15)] = W1[i];
    __syncthreads();

    const int lane = threadIdx.x & 31;
    int warp = (blockIdx.x * 256 + threadIdx.x) >> 5;
    const int nw = (gridDim.x * 256) >> 5;

    for (int row = warp; row < n; row += nw) {
        const float* xr = x + (size_t)row * IN_F + lane;
        float xv[16];
        #pragma unroll
        for (int i = 0; i < 16; i++) xv[i] = xr[i * 32];   // coalesced, MLP=16

        unsigned long long acc[8];
        #pragma unroll
        for (int jj = 0; jj < 8; jj++) acc[jj] = 0ull;

        #pragma unroll
        for (int i = 0; i < 16; i++) {
            const int k = lane + i * 32;
            unsigned long long xx;
            PACK2(xx, xv[i]);
            const unsigned long long* wr =
                (const unsigned long long*)(Wp + k * 18);   // 72B-aligned (8 | 72)
            #pragma unroll
            for (int jj = 0; jj < 8; jj++) FMA2(acc[jj], xx, wr[jj], acc[jj]);
        }

        // butterfly reduce across 32 lanes (all lanes end with the full sums)
        #pragma unroll
        for (int off = 16; off >= 1; off >>= 1) {
            #pragma unroll
            for (int jj = 0; jj < 8; jj++) {
                unsigned long long o = __shfl_xor_sync(0xffffffffu, acc[jj], off);
                ADD2(acc[jj], acc[jj], o);
            }
        }

        const float di = s_dinv[row];
        unsigned long long dd;
        PACK2(dd, di);
        #pragma unroll
        for (int jj = 0; jj < 8; jj++) MUL2(acc[jj], acc[jj], dd);

        if (lane < 8) {                 // lanes 0-3 -> g1, lanes 4-7 -> agg1 (self-loop init)
            const int m = lane & 3;
            unsigned long long p0 = acc[2 * m], p1 = acc[2 * m + 1];
            float4 v;
            v.x = __uint_as_float((unsigned)p0);
            v.y = __uint_as_float((unsigned)(p0 >> 32));
            v.z = __uint_as_float((unsigned)p1);
            v.w = __uint_as_float((unsigned)(p1 >> 32));
            (lane < 4 ? s_g1 : s_agg1)[(size_t)row * 4 + m] = v;
        }
    }
}

// ---------------- layer-1 scatter: agg1[dst] += g1[src] ----------------
__global__ void k_scatter1(const int* __restrict__ src, const int* __restrict__ dst, int e) {
    int i = blockIdx.x * blockDim.x + threadIdx.x;
    if (i >= e) return;
    const int s = src[i], d = dst[i];
    const float4* g = s_g1 + (size_t)s * 4;
    float4 v0 = __ldg(g + 0), v1 = __ldg(g + 1), v2 = __ldg(g + 2), v3 = __ldg(g + 3);
    float4* a = s_agg1 + (size_t)d * 4;
    RED4(a + 0, v0.x, v0.y, v0.z, v0.w);
    RED4(a + 1, v1.x, v1.y, v1.z, v1.w);
    RED4(a + 2, v2.x, v2.y, v2.z, v2.w);
    RED4(a + 3, v3.x, v3.y, v3.z, v3.w);
}

// ---------------- mid: relu(dinv*agg1 + b1) @ W2, scale by dinv, init agg2 ----------------
__global__ void k_mid(const float* __restrict__ b1, const float* __restrict__ W2, int n) {
    __shared__ float W2s[HID * NCLS];
    __shared__ float b1s[HID];
    if (threadIdx.x < HID * NCLS) W2s[threadIdx.x] = W2[threadIdx.x];
    if (threadIdx.x < HID)        b1s[threadIdx.x] = b1[threadIdx.x];
    __syncthreads();

    int i = blockIdx.x * blockDim.x + threadIdx.x;
    if (i >= n) return;

    const float di = s_dinv[i];
    float v[HID];
    #pragma unroll
    for (int m = 0; m < 4; m++) {
        float4 t = s_agg1[(size_t)i * 4 + m];
        v[4 * m + 0] = fmaxf(fmaf(di, t.x, b1s[4 * m + 0]), 0.f);
        v[4 * m + 1] = fmaxf(fmaf(di, t.y, b1s[4 * m + 1]), 0.f);
        v[4 * m + 2] = fmaxf(fmaf(di, t.z, b1s[4 * m + 2]), 0.f);
        v[4 * m + 3] = fmaxf(fmaf(di, t.w, b1s[4 * m + 3]), 0.f);
    }

    float u[NCLS] = {0.f, 0.f, 0.f, 0.f, 0.f, 0.f, 0.f};
    #pragma unroll
    for (int j = 0; j < HID; j++) {
        #pragma unroll
        for (int c = 0; c < NCLS; c++)
            u[c] = fmaf(v[j], W2s[j * NCLS + c], u[c]);   // smem broadcast reads
    }

    float4 o0 = make_float4(di * u[0], di * u[1], di * u[2], di * u[3]);
    float4 o1 = make_float4(di * u[4], di * u[5], di * u[6], 0.f);
    s_g2  [(size_t)i * 2 + 0] = o0;  s_g2  [(size_t)i * 2 + 1] = o1;
    s_agg2[(size_t)i * 2 + 0] = o0;  s_agg2[(size_t)i * 2 + 1] = o1;  // self-loop init
}

// ---------------- layer-2 scatter: agg2[dst] += g2[src] ----------------
__global__ void k_scatter2(const int* __restrict__ src, const int* __restrict__ dst, int e) {
    int i = blockIdx.x * blockDim.x + threadIdx.x;
    if (i >= e) return;
    const int s = src[i], d = dst[i];
    const float4* g = s_g2 + (size_t)s * 2;
    float4 v0 = __ldg(g + 0), v1 = __ldg(g + 1);
    float4* a = s_agg2 + (size_t)d * 2;
    RED4(a + 0, v0.x, v0.y, v0.z, v0.w);
    RED4(a + 1, v1.x, v1.y, v1.z, v1.w);
}

// ---------------- final: out = dinv*agg2 + b2 ----------------
__global__ void k_final(const float* __restrict__ b2, float* __restrict__ out, int n) {
    int idx = blockIdx.x * blockDim.x + threadIdx.x;
    if (idx >= n * NCLS) return;
    const int i = idx / NCLS, c = idx - i * NCLS;
    const float* a2 = (const float*)s_agg2;
    out[idx] = fmaf(s_dinv[i], a2[(size_t)i * 8 + c], __ldg(b2 + c));
}

extern "C" void kernel_launch(void* const* d_in, const int* in_sizes, int n_in,
                              void* d_out, int out_size) {
    const float* x  = (const float*)d_in[0];
    const int*   ei = (const int*)  d_in[1];
    const float* W1 = (const float*)d_in[2];
    const float* b1 = (const float*)d_in[3];
    const float* W2 = (const float*)d_in[4];
    const float* b2 = (const float*)d_in[5];
    float* out = (float*)d_out;

    const int n = in_sizes[0] / IN_F;     // 100000
    const int e = in_sizes[1] / 2;        // 3200000
    const int* src = ei;
    const int* dst = ei + e;

    const int nb  = (n + 255) / 256;
    const int eb  = (e + 255) / 256;

    k_init    <<<nb, 256>>>(n);
    k_deg     <<<eb, 256>>>(dst, e);
    k_rsqrt   <<<nb, 256>>>(n);
    k_gemm1   <<<592, 256>>>(x, W1, n);
    k_scatter1<<<eb, 256>>>(src, dst, e);
    k_mid     <<<nb, 256>>>(b1, W2, n);
    k_scatter2<<<eb, 256>>>(src, dst, e);
    k_final   <<<(n * NCLS + 255) / 256, 256>>>(b2, out, n);
}

// round 2
// speedup vs baseline: 1.2160x; 1.2160x over previous
#include <cuda_runtime.h>
#include <cstdint>

#define N_MAX 100000
#define IN_F  512
#define HID   16
#define NCLS  7

// ---- scratch (no allocations allowed) ----
__device__ float  s_dinv[N_MAX];
__device__ float4 s_g1  [N_MAX * 4];   // [N][16] floats: dinv*x@W1
__device__ float4 s_agg1[N_MAX * 4];   // layer-1 accumulator
__device__ float4 s_g2  [N_MAX * 2];   // [N][8] floats (col 7 = 0 pad)
__device__ float4 s_agg2[N_MAX * 2];   // layer-2 accumulator

// ---- f32x2 packed math (sm_100+) ----
#define FMA2(d, a, b, c) asm("fma.rn.f32x2 %0, %1, %2, %3;" : "=l"(d) : "l"(a), "l"(b), "l"(c))
#define MUL2(d, a, b)    asm("mul.rn.f32x2 %0, %1, %2;"     : "=l"(d) : "l"(a), "l"(b))
#define PACK2(d, s)      asm("mov.b64 %0, {%1, %1};"        : "=l"(d) : "r"(__float_as_uint(s)))

// vector reduction to global (sm_90+): one 16B L2 atomic instead of 4 scalar ones
#define RED4(p, a, b, c, d) \
    asm volatile("red.global.add.v4.f32 [%0], {%1, %2, %3, %4};" \
                 :: "l"(p), "f"(a), "f"(b), "f"(c), "f"(d) : "memory")

// ---------------- degree / dinv ----------------
__global__ void k_init(int n) {
    int i = blockIdx.x * blockDim.x + threadIdx.x;
    if (i < n) s_dinv[i] = 1.0f;                 // self-loop counts once
}

__global__ void k_deg(const int* __restrict__ dst, int e) {
    int i = blockIdx.x * blockDim.x + threadIdx.x;
    if (i < e) atomicAdd(&s_dinv[dst[i]], 1.0f);
}

__global__ void k_rsqrt(int n) {
    int i = blockIdx.x * blockDim.x + threadIdx.x;
    if (i < n) s_dinv[i] = rsqrtf(s_dinv[i]);    // deg >= 1 always
}

// ---------------- layer-1 GEMM: g1[i] = dinv[i] * (x[i] @ W1) ----------------
// Thread-per-row, 16-col (8 f32x2) register accumulator. W (512x16 = 32KB)
// resident in smem; all lanes of a warp walk the same k => W reads are
// conflict-free broadcasts, amortized over 32 rows. X staged through smem in
// 256row x 32k tiles with pitch 33 (bank = (row + k) % 32 => conflict-free).
#define G1_ROWS 256
#define G1_KT   32
#define G1_PIT  33

__global__ void __launch_bounds__(256, 3) k_gemm1(const float* __restrict__ x,
                                                  const float* __restrict__ W1, int n) {
    __shared__ float Ws[IN_F * HID];           // 32 KB, [k][j] row-major
    __shared__ float Xs[G1_ROWS * G1_PIT];     // 33.8 KB

    const int t = threadIdx.x;

    // load full W once (coalesced float4)
    {
        const float4* Wg = (const float4*)W1;
        float4*       Wd = (float4*)Ws;
        #pragma unroll
        for (int i = 0; i < (IN_F * HID / 4) / 256; i++)
            Wd[i * 256 + t] = Wg[i * 256 + t];
    }
    __syncthreads();

    const int rowbase = blockIdx.x * G1_ROWS;
    const int myrow   = rowbase + t;
    const bool live   = (myrow < n);

    unsigned long long acc[8];
    #pragma unroll
    for (int jj = 0; jj < 8; jj++) acc[jj] = 0ull;

    for (int k0 = 0; k0 < IN_F; k0 += G1_KT) {
        // ---- stage X tile: 256 rows x 32 k, coalesced float4 loads ----
        __syncthreads();
        #pragma unroll
        for (int it = 0; it < 8; it++) {                 // 2048 float4 / 256 thr
            const int lin = it * 256 + t;
            const int row = lin >> 3;                    // 8 float4 per row
            const int q   = lin & 7;
            float4 v = make_float4(0.f, 0.f, 0.f, 0.f);
            if (rowbase + row < n)
                v = *(const float4*)(x + (size_t)(rowbase + row) * IN_F + k0 + q * 4);
            float* dsts = Xs + row * G1_PIT + q * 4;
            dsts[0] = v.x; dsts[1] = v.y; dsts[2] = v.z; dsts[3] = v.w;
        }
        __syncthreads();

        // ---- compute: 32 k-steps, W via uniform-address LDS.128 broadcast ----
        const float* xr = Xs + t * G1_PIT;
        #pragma unroll
        for (int k = 0; k < G1_KT; k++) {
            unsigned long long xx;
            PACK2(xx, xr[k]);
            const ulonglong2* wr = (const ulonglong2*)(Ws + (k0 + k) * HID);
            #pragma unroll
            for (int q = 0; q < 4; q++) {
                ulonglong2 w = wr[q];
                FMA2(acc[2 * q + 0], xx, w.x, acc[2 * q + 0]);
                FMA2(acc[2 * q + 1], xx, w.y, acc[2 * q + 1]);
            }
        }
    }

    if (!live) return;

    const float di = s_dinv[myrow];
    unsigned long long dd;
    PACK2(dd, di);
    #pragma unroll
    for (int jj = 0; jj < 8; jj++) MUL2(acc[jj], acc[jj], dd);

    #pragma unroll
    for (int m = 0; m < 4; m++) {
        unsigned long long p0 = acc[2 * m], p1 = acc[2 * m + 1];
        float4 v;
        v.x = __uint_as_float((unsigned)p0);
        v.y = __uint_as_float((unsigned)(p0 >> 32));
        v.z = __uint_as_float((unsigned)p1);
        v.w = __uint_as_float((unsigned)(p1 >> 32));
        s_g1  [(size_t)myrow * 4 + m] = v;
        s_agg1[(size_t)myrow * 4 + m] = v;   // self-loop init
    }
}

// ---------------- layer-1 scatter: agg1[dst] += g1[src] ----------------
__global__ void k_scatter1(const int* __restrict__ src, const int* __restrict__ dst, int e) {
    int i = blockIdx.x * blockDim.x + threadIdx.x;
    if (i >= e) return;
    const int s = src[i], d = dst[i];
    const float4* g = s_g1 + (size_t)s * 4;
    float4 v0 = __ldg(g + 0), v1 = __ldg(g + 1), v2 = __ldg(g + 2), v3 = __ldg(g + 3);
    float4* a = s_agg1 + (size_t)d * 4;
    RED4(a + 0, v0.x, v0.y, v0.z, v0.w);
    RED4(a + 1, v1.x, v1.y, v1.z, v1.w);
    RED4(a + 2, v2.x, v2.y, v2.z, v2.w);
    RED4(a + 3, v3.x, v3.y, v3.z, v3.w);
}

// ---------------- mid: relu(dinv*agg1 + b1) @ W2, scale by dinv, init agg2 ----------------
__global__ void k_mid(const float* __restrict__ b1, const float* __restrict__ W2, int n) {
    __shared__ float W2s[HID * NCLS];
    __shared__ float b1s[HID];
    if (threadIdx.x < HID * NCLS) W2s[threadIdx.x] = W2[threadIdx.x];
    if (threadIdx.x < HID)        b1s[threadIdx.x] = b1[threadIdx.x];
    __syncthreads();

    int i = blockIdx.x * blockDim.x + threadIdx.x;
    if (i >= n) return;

    const float di = s_dinv[i];
    float v[HID];
    #pragma unroll
    for (int m = 0; m < 4; m++) {
        float4 tt = s_agg1[(size_t)i * 4 + m];
        v[4 * m + 0] = fmaxf(fmaf(di, tt.x, b1s[4 * m + 0]), 0.f);
        v[4 * m + 1] = fmaxf(fmaf(di, tt.y, b1s[4 * m + 1]), 0.f);
        v[4 * m + 2] = fmaxf(fmaf(di, tt.z, b1s[4 * m + 2]), 0.f);
        v[4 * m + 3] = fmaxf(fmaf(di, tt.w, b1s[4 * m + 3]), 0.f);
    }

    float u[NCLS] = {0.f, 0.f, 0.f, 0.f, 0.f, 0.f, 0.f};
    #pragma unroll
    for (int j = 0; j < HID; j++) {
        #pragma unroll
        for (int c = 0; c < NCLS; c++)
            u[c] = fmaf(v[j], W2s[j * NCLS + c], u[c]);   // smem broadcast reads
    }

    float4 o0 = make_float4(di * u[0], di * u[1], di * u[2], di * u[3]);
    float4 o1 = make_float4(di * u[4], di * u[5], di * u[6], 0.f);
    s_g2  [(size_t)i * 2 + 0] = o0;  s_g2  [(size_t)i * 2 + 1] = o1;
    s_agg2[(size_t)i * 2 + 0] = o0;  s_agg2[(size_t)i * 2 + 1] = o1;  // self-loop init
}

// ---------------- layer-2 scatter: agg2[dst] += g2[src] ----------------
__global__ void k_scatter2(const int* __restrict__ src, const int* __restrict__ dst, int e) {
    int i = blockIdx.x * blockDim.x + threadIdx.x;
    if (i >= e) return;
    const int s = src[i], d = dst[i];
    const float4* g = s_g2 + (size_t)s * 2;
    float4 v0 = __ldg(g + 0), v1 = __ldg(g + 1);
    float4* a = s_agg2 + (size_t)d * 2;
    RED4(a + 0, v0.x, v0.y, v0.z, v0.w);
    RED4(a + 1, v1.x, v1.y, v1.z, v1.w);
}

// ---------------- final: out = dinv*agg2 + b2 ----------------
__global__ void k_final(const float* __restrict__ b2, float* __restrict__ out, int n) {
    int idx = blockIdx.x * blockDim.x + threadIdx.x;
    if (idx >= n * NCLS) return;
    const int i = idx / NCLS, c = idx - i * NCLS;
    const float* a2 = (const float*)s_agg2;
    out[idx] = fmaf(s_dinv[i], a2[(size_t)i * 8 + c], __ldg(b2 + c));
}

extern "C" void kernel_launch(void* const* d_in, const int* in_sizes, int n_in,
                              void* d_out, int out_size) {
    const float* x  = (const float*)d_in[0];
    const int*   ei = (const int*)  d_in[1];
    const float* W1 = (const float*)d_in[2];
    const float* b1 = (const float*)d_in[3];
    const float* W2 = (const float*)d_in[4];
    const float* b2 = (const float*)d_in[5];
    float* out = (float*)d_out;

    const int n = in_sizes[0] / IN_F;     // 100000
    const int e = in_sizes[1] / 2;        // 3200000
    const int* src = ei;
    const int* dst = ei + e;

    const int nb  = (n + 255) / 256;
    const int eb  = (e + 255) / 256;
    const int gb  = (n + G1_ROWS - 1) / G1_ROWS;

    k_init    <<<nb, 256>>>(n);
    k_deg     <<<eb, 256>>>(dst, e);
    k_rsqrt   <<<nb, 256>>>(n);
    k_gemm1   <<<gb, 256>>>(x, W1, n);
    k_scatter1<<<eb, 256>>>(src, dst, e);
    k_mid     <<<nb, 256>>>(b1, W2, n);
    k_scatter2<<<eb, 256>>>(src, dst, e);
    k_final   <<<(n * NCLS + 255) / 256, 256>>>(b2, out, n);
}

// round 4
// speedup vs baseline: 1.2434x; 1.0225x over previous
#include <cuda_runtime.h>
#include <cstdint>

#define N_MAX  100000
#define E_MAXC 3200000
#define IN_F   512
#define HID    16
#define NCLS   7

typedef unsigned long long ull;

// ---- scratch (no allocations allowed) ----
__device__ int    s_cnt[N_MAX];       // in-degree (excl. self-loop)
__device__ int    s_row[N_MAX];       // CSR row start (exclusive prefix of cnt)
__device__ int    s_cur[N_MAX];       // fill cursor
__device__ int    s_bsum[512];        // block sums for scan
__device__ float  s_dinv[N_MAX];
__device__ float4 s_g1[N_MAX * 4];    // [N][16]: dinv * (x@W1)
__device__ float4 s_g2[N_MAX * 2];    // [N][8] (col 7 pad): dinv * (h@W2)
__device__ int    s_csr[E_MAXC];      // src indices grouped by dst

// ---- f32x2 packed math (sm_100+) ----
#define FMA2(d, a, b, c) asm("fma.rn.f32x2 %0, %1, %2, %3;" : "=l"(d) : "l"(a), "l"(b), "l"(c))
#define ADD2(d, a, b)    asm("add.rn.f32x2 %0, %1, %2;"     : "=l"(d) : "l"(a), "l"(b))
#define MUL2(d, a, b)    asm("mul.rn.f32x2 %0, %1, %2;"     : "=l"(d) : "l"(a), "l"(b))
#define PACK2(d, s)      asm("mov.b64 %0, {%1, %1};"        : "=l"(d) : "r"(__float_as_uint(s)))
#define PACKAB(d, lo, hi) asm("mov.b64 %0, {%1, %2};"       : "=l"(d) : "f"(lo), "f"(hi))

__device__ __forceinline__ float lo32(ull p) { return __uint_as_float((unsigned)p); }
__device__ __forceinline__ float hi32(ull p) { return __uint_as_float((unsigned)(p >> 32)); }

// ================= degree histogram + CSR build =================
__global__ void k_zero(int n) {
    int i = blockIdx.x * blockDim.x + threadIdx.x;
    if (i < n) s_cnt[i] = 0;
}

__global__ void k_hist(const int* __restrict__ dst, int e) {
    int i = blockIdx.x * blockDim.x + threadIdx.x;
    if (i < e) atomicAdd(&s_cnt[dst[i]], 1);
}

__global__ void k_scanA(int n) {              // per-block inclusive scan
    __shared__ int sh[256];
    const int t = threadIdx.x;
    const int i = blockIdx.x * 256 + t;
    int v = (i < n) ? s_cnt[i] : 0;
    sh[t] = v;
    __syncthreads();
    #pragma unroll
    for (int off = 1; off < 256; off <<= 1) {
        int add = (t >= off) ? sh[t - off] : 0;
        __syncthreads();
        sh[t] += add;
        __syncthreads();
    }
    if (i < n) s_row[i] = sh[t] - v;          // exclusive within block
    if (t == 255) s_bsum[blockIdx.x] = sh[255];
}

__global__ void k_scanB(int nb) {             // scan of block sums (nb <= 512)
    __shared__ int sh[512];
    const int t = threadIdx.x;
    int v = (t < nb) ? s_bsum[t] : 0;
    sh[t] = v;
    __syncthreads();
    #pragma unroll
    for (int off = 1; off < 512; off <<= 1) {
        int add = (t >= off) ? sh[t - off] : 0;
        __syncthreads();
        sh[t] += add;
        __syncthreads();
    }
    if (t < nb) s_bsum[t] = sh[t] - v;        // exclusive block prefix
}

__global__ void k_scanC(int n) {              // finalize row starts + dinv
    int i = blockIdx.x * blockDim.x + threadIdx.x;
    if (i >= n) return;
    int st = s_row[i] + s_bsum[i >> 8];
    s_row[i] = st;
    s_cur[i] = st;
    s_dinv[i] = rsqrtf((float)(s_cnt[i] + 1));   // +1 self-loop
}

__global__ void k_fill(const int* __restrict__ src, const int* __restrict__ dst, int e) {
    int i = blockIdx.x * blockDim.x + threadIdx.x;
    if (i >= e) return;
    int p = atomicAdd(&s_cur[dst[i]], 1);
    s_csr[p] = src[i];
}

// ================= layer-1 GEMM: g1[i] = dinv[i] * (x[i] @ W1) =================
// Thread-per-row, 8 f32x2 accumulators. W (32KB) resident in smem, read as
// warp-uniform LDS.128 broadcasts. X streamed in 256x8 tiles via cp.async
// double buffering. Swizzle q' = q ^ ((row>>1)&1) keeps 16B vectors intact and
// makes both staging stores and compute LDS.128 conflict-free.
#define G1_ROWS 256

#define STAGE(buf, k0)                                                             \
    {                                                                              \
        _Pragma("unroll")                                                          \
        for (int j = 0; j < 2; j++) {                                              \
            int row  = j * 128 + sr;                                               \
            int grow = rowbase + row;                                              \
            int qp   = sq ^ ((row >> 1) & 1);                                      \
            unsigned dstp = (unsigned)__cvta_generic_to_shared(                    \
                &Xs[(buf) * 2048 + row * 8 + qp * 4]);                             \
            const float* gp = x + (size_t)grow * IN_F + (k0) + sq * 4;             \
            if (grow < n)                                                          \
                asm volatile("cp.async.ca.shared.global [%0], [%1], 16;"           \
                             :: "r"(dstp), "l"(gp));                               \
        }                                                                          \
    }

__global__ void __launch_bounds__(256, 4) k_gemm1(const float* __restrict__ x,
                                                  const float* __restrict__ W1, int n) {
    __shared__ float  Ws[IN_F * HID];   // 32 KB
    __shared__ float4 Xs4[2][512];      // 2 x 8 KB  (total static smem = 48 KB)
    float* Xs = (float*)Xs4;

    const int t = threadIdx.x;
    const int rowbase = blockIdx.x * G1_ROWS;
    const int sr = t >> 1, sq = t & 1;  // staging mapping

    STAGE(0, 0);
    asm volatile("cp.async.commit_group;");

    #pragma unroll
    for (int i = 0; i < 8; i++)
        ((float4*)Ws)[i * 256 + t] = ((const float4*)W1)[i * 256 + t];

    ull acc[8] = {0, 0, 0, 0, 0, 0, 0, 0};
    const int ss = (t >> 1) & 1;        // compute-side swizzle for own row (=t)

    for (int tile = 0; tile < 64; tile++) {
        if (tile < 63) STAGE((tile + 1) & 1, (tile + 1) * 8);
        asm volatile("cp.async.commit_group;");
        asm volatile("cp.async.wait_group 1;");
        __syncthreads();

        const float4* xr = (const float4*)&Xs[(tile & 1) * 2048 + t * 8];
        #pragma unroll
        for (int qq = 0; qq < 2; qq++) {
            float4 xv = xr[qq ^ ss];
            #pragma unroll
            for (int jj = 0; jj < 4; jj++) {
                ull xx;
                PACK2(xx, ((const float*)&xv)[jj]);
                const ulonglong2* wr =
                    (const ulonglong2*)(Ws + (tile * 8 + qq * 4 + jj) * HID);
                ulonglong2 wa = wr[0], wb = wr[1], wc = wr[2], wd = wr[3];
                FMA2(acc[0], xx, wa.x, acc[0]); FMA2(acc[1], xx, wa.y, acc[1]);
                FMA2(acc[2], xx, wb.x, acc[2]); FMA2(acc[3], xx, wb.y, acc[3]);
                FMA2(acc[4], xx, wc.x, acc[4]); FMA2(acc[5], xx, wc.y, acc[5]);
                FMA2(acc[6], xx, wd.x, acc[6]); FMA2(acc[7], xx, wd.y, acc[7]);
            }
        }
        __syncthreads();
    }

    const int myrow = rowbase + t;
    if (myrow >= n) return;

    const float di = s_dinv[myrow];
    ull dd;
    PACK2(dd, di);
    #pragma unroll
    for (int jj = 0; jj < 8; jj++) MUL2(acc[jj], acc[jj], dd);

    #pragma unroll
    for (int m = 0; m < 4; m++) {
        float4 v;
        v.x = lo32(acc[2 * m]);     v.y = hi32(acc[2 * m]);
        v.z = lo32(acc[2 * m + 1]); v.w = hi32(acc[2 * m + 1]);
        s_g1[(size_t)myrow * 4 + m] = v;
    }
}

// ================= layer-1 gather + fused mid =================
// 4 lanes per dst node; lane m owns cols [4m, 4m+4). acc init = g1[dst] (self
// loop), add g1[src] over the CSR row, then h = relu(dinv*acc + b1), partial
// u = h@W2 per lane, 4-lane butterfly reduce, g2 = dinv*u.
__global__ void __launch_bounds__(256) k_gather1(const float* __restrict__ b1,
                                                 const float* __restrict__ W2, int n) {
    __shared__ float W2s[HID * NCLS];
    __shared__ float b1s[HID];
    const int t = threadIdx.x;
    if (t < HID * NCLS) W2s[t] = W2[t];
    if (t < HID)        b1s[t] = b1[t];
    __syncthreads();

    const int g = (blockIdx.x * 256 + t) >> 2;
    const int m = t & 3;
    if (g >= n) return;

    const ulonglong2* G1 = (const ulonglong2*)s_g1;
    ulonglong2 acc = G1[(size_t)g * 4 + m];
    const int start = s_row[g], cnt = s_cnt[g];
    const int* cp = s_csr + start;

    int it = 0;
    for (; it + 3 < cnt; it += 4) {
        int i0 = __ldg(cp + it), i1 = __ldg(cp + it + 1);
        int i2 = __ldg(cp + it + 2), i3 = __ldg(cp + it + 3);
        ulonglong2 v0 = __ldg(&G1[(size_t)i0 * 4 + m]);
        ulonglong2 v1 = __ldg(&G1[(size_t)i1 * 4 + m]);
        ulonglong2 v2 = __ldg(&G1[(size_t)i2 * 4 + m]);
        ulonglong2 v3 = __ldg(&G1[(size_t)i3 * 4 + m]);
        ADD2(acc.x, acc.x, v0.x); ADD2(acc.y, acc.y, v0.y);
        ADD2(acc.x, acc.x, v1.x); ADD2(acc.y, acc.y, v1.y);
        ADD2(acc.x, acc.x, v2.x); ADD2(acc.y, acc.y, v2.y);
        ADD2(acc.x, acc.x, v3.x); ADD2(acc.y, acc.y, v3.y);
    }
    for (; it < cnt; it++) {
        int i0 = __ldg(cp + it);
        ulonglong2 v0 = __ldg(&G1[(size_t)i0 * 4 + m]);
        ADD2(acc.x, acc.x, v0.x); ADD2(acc.y, acc.y, v0.y);
    }

    const float di = s_dinv[g];
    float h[4];
    h[0] = fmaxf(fmaf(di, lo32(acc.x), b1s[m * 4 + 0]), 0.f);
    h[1] = fmaxf(fmaf(di, hi32(acc.x), b1s[m * 4 + 1]), 0.f);
    h[2] = fmaxf(fmaf(di, lo32(acc.y), b1s[m * 4 + 2]), 0.f);
    h[3] = fmaxf(fmaf(di, hi32(acc.y), b1s[m * 4 + 3]), 0.f);

    float u[8] = {0.f, 0.f, 0.f, 0.f, 0.f, 0.f, 0.f, 0.f};
    #pragma unroll
    for (int jj = 0; jj < 4; jj++) {
        const int j = m * 4 + jj;
        #pragma unroll
        for (int c = 0; c < NCLS; c++)
            u[c] = fmaf(h[jj], W2s[j * NCLS + c], u[c]);
    }

    ull p[4];
    PACKAB(p[0], u[0], u[1]);
    PACKAB(p[1], u[2], u[3]);
    PACKAB(p[2], u[4], u[5]);
    PACKAB(p[3], u[6], u[7]);
    #pragma unroll
    for (int off = 1; off <= 2; off <<= 1) {
        #pragma unroll
        for (int q = 0; q < 4; q++) {
            ull o = __shfl_xor_sync(0xffffffffu, p[q], off);
            ADD2(p[q], p[q], o);
        }
    }
    ull dd;
    PACK2(dd, di);
    #pragma unroll
    for (int q = 0; q < 4; q++) MUL2(p[q], p[q], dd);

    if (m == 0) {
        float4 v = make_float4(lo32(p[0]), hi32(p[0]), lo32(p[1]), hi32(p[1]));
        s_g2[(size_t)g * 2 + 0] = v;
    } else if (m == 1) {
        float4 v = make_float4(lo32(p[2]), hi32(p[2]), lo32(p[3]), hi32(p[3]));
        s_g2[(size_t)g * 2 + 1] = v;
    }
}

// ================= layer-2 gather + fused final output =================
// 4 lanes per dst node; lane m owns cols [2m, 2m+2) of the 8-wide padded g2.
__global__ void __launch_bounds__(256) k_gather2(const float* __restrict__ b2,
                                                 float* __restrict__ out, int n) {
    const int t = threadIdx.x;
    const int g = (blockIdx.x * 256 + t) >> 2;
    const int m = t & 3;
    if (g >= n) return;

    const ull* G2 = (const ull*)s_g2;
    ull acc = G2[(size_t)g * 4 + m];
    const int start = s_row[g], cnt = s_cnt[g];
    const int* cp = s_csr + start;

    int it = 0;
    for (; it + 3 < cnt; it += 4) {
        int i0 = __ldg(cp + it), i1 = __ldg(cp + it + 1);
        int i2 = __ldg(cp + it + 2), i3 = __ldg(cp + it + 3);
        ull v0 = __ldg(&G2[(size_t)i0 * 4 + m]);
        ull v1 = __ldg(&G2[(size_t)i1 * 4 + m]);
        ull v2 = __ldg(&G2[(size_t)i2 * 4 + m]);
        ull v3 = __ldg(&G2[(size_t)i3 * 4 + m]);
        ADD2(acc, acc, v0); ADD2(acc, acc, v1);
        ADD2(acc, acc, v2); ADD2(acc, acc, v3);
    }
    for (; it < cnt; it++) {
        int i0 = __ldg(cp + it);
        ull v0 = __ldg(&G2[(size_t)i0 * 4 + m]);
        ADD2(acc, acc, v0);
    }

    const float di = s_dinv[g];
    const int c0 = m * 2;
    float* orow = out + (size_t)g * NCLS;
    orow[c0] = fmaf(di, lo32(acc), __ldg(b2 + c0));
    if (c0 + 1 < NCLS)
        orow[c0 + 1] = fmaf(di, hi32(acc), __ldg(b2 + c0 + 1));
}

extern "C" void kernel_launch(void* const* d_in, const int* in_sizes, int n_in,
                              void* d_out, int out_size) {
    const float* x  = (const float*)d_in[0];
    const int*   ei = (const int*)  d_in[1];
    const float* W1 = (const float*)d_in[2];
    const float* b1 = (const float*)d_in[3];
    const float* W2 = (const float*)d_in[4];
    const float* b2 = (const float*)d_in[5];
    float* out = (float*)d_out;

    const int n = in_sizes[0] / IN_F;     // 100000
    const int e = in_sizes[1] / 2;        // 3200000
    const int* src = ei;
    const int* dst = ei + e;

    const int nb = (n + 255) / 256;
    const int eb = (e + 255) / 256;
    const int gb = (n + G1_ROWS - 1) / G1_ROWS;
    const int g4 = (4 * n + 255) / 256;

    k_zero   <<<nb, 256>>>(n);
    k_hist   <<<eb, 256>>>(dst, e);
    k_scanA  <<<nb, 256>>>(n);
    k_scanB  <<<1, 512>>>(nb);
    k_scanC  <<<nb, 256>>>(n);
    k_fill   <<<eb, 256>>>(src, dst, e);
    k_gemm1  <<<gb, 256>>>(x, W1, n);
    k_gather1<<<g4, 256>>>(b1, W2, n);
    k_gather2<<<g4, 256>>>(b2, out, n);
}